// round 3
// baseline (speedup 1.0000x reference)
#include <cuda_runtime.h>

// Problem constants
#define D        64
#define S        64
#define BSZ      512
#define LTW      2016          // d*(d-1)/2
#define ZROW     6112          // lt + d*d
#define OUT_ELEMS (BSZ * S * D) // 2097152, z_adj follows at this offset

typedef unsigned long long u64;

// ---------------- f32x2 packed-math helpers (sm_100+) ----------------
__device__ __forceinline__ u64 pack2(float lo, float hi) {
    u64 r; asm("mov.b64 %0, {%1,%2};" : "=l"(r) : "f"(lo), "f"(hi)); return r;
}
__device__ __forceinline__ void unpack2(u64 v, float& lo, float& hi) {
    asm("mov.b64 {%0,%1}, %2;" : "=f"(lo), "=f"(hi) : "l"(v));
}
__device__ __forceinline__ u64 fma2(u64 a, u64 b, u64 c) {
    u64 d; asm("fma.rn.f32x2 %0, %1, %2, %3;" : "=l"(d) : "l"(a), "l"(b), "l"(c)); return d;
}
__device__ __forceinline__ u64 relu2(u64 v) {
    float lo, hi; unpack2(v, lo, hi);
    lo = fmaxf(lo, 0.0f); hi = fmaxf(hi, 0.0f);
    return pack2(lo, hi);
}

// ---------------- Kernel A: z_adj[s] = z_p^T @ z_lt @ z_p ----------------
// One block per s, 256 threads. Shared: lt, p, tmp (each 64x64 fp32).
__global__ void zadj_kernel(const float* __restrict__ z, float* __restrict__ adj_out) {
    extern __shared__ float sm[];
    float* lt  = sm;           // 4096
    float* p   = sm + 4096;    // 4096
    float* tmp = sm + 8192;    // 4096
    const int s   = blockIdx.x;
    const int tid = threadIdx.x;
    const float* zs = z + s * ZROW;

    // zero lt, load p
    for (int e = tid; e < 4096; e += 256) {
        lt[e] = 0.0f;
        p[e]  = zs[LTW + e];   // z_p[r][i] row-major
    }
    __syncthreads();

    // scatter strictly-lower-triangular entries: k = i*(i-1)/2 + j, j < i
    for (int k = tid; k < LTW; k += 256) {
        int i = (int)((sqrtf(8.0f * (float)k + 1.0f) + 1.0f) * 0.5f);
        while (i * (i - 1) / 2 > k)       --i;
        while ((i + 1) * i / 2 <= k)      ++i;
        int j = k - i * (i - 1) / 2;
        lt[i * 64 + j] = zs[k];
    }
    __syncthreads();

    // tmp = lt @ p   (lt strictly lower: t < r)
    for (int e = tid; e < 4096; e += 256) {
        int r = e >> 6, j = e & 63;
        float acc = 0.0f;
        for (int t = 0; t < r; ++t)
            acc += lt[r * 64 + t] * p[t * 64 + j];
        tmp[e] = acc;
    }
    __syncthreads();

    // adj = p^T @ tmp
    for (int e = tid; e < 4096; e += 256) {
        int i = e >> 6, j = e & 63;
        float acc = 0.0f;
        #pragma unroll 8
        for (int r = 0; r < 64; ++r)
            acc += p[r * 64 + i] * tmp[r * 64 + j];
        adj_out[s * 4096 + e] = acc;
    }
}

// ---------------- Kernel B: fused 4-layer channel MLP ----------------
// Grid (c=64, s=64); 128 threads. Each thread handles 4 batch rows as 2 f32x2 pairs.
// Shared layout (floats):
//   xs   [512*65]  (pad-65 -> conflict-free column reads)
//   zc   [64]      z_adj[s, i, c]
//   w0d  [4096]    W0[c] lane-duplicated   (o*64+i -> 2 floats)
//   w1d  [2048]    W1[c] dup
//   w2d  [2048]    W2[c] dup
//   w3d  [64]      W3[c] dup
//   bb0/bb1/bb2 [64 each], bb3 [2]  biases dup
#define XS_OFF   0
#define ZC_OFF   33280
#define W0_OFF   33344
#define W1_OFF   37440
#define W2_OFF   39488
#define W3_OFF   41536
#define B0_OFF   41600
#define B1_OFF   41664
#define B2_OFF   41728
#define B3_OFF   41792
#define SMEM_FLOATS 41794
#define SMEM_BYTES  (41794 * 4 + 56)   // 167232, 8B-rounded

__global__ void __launch_bounds__(128, 1) mlp_kernel(
    const float* __restrict__ x,  const float* __restrict__ adj,
    const float* __restrict__ W0, const float* __restrict__ b0,
    const float* __restrict__ W1, const float* __restrict__ b1,
    const float* __restrict__ W2, const float* __restrict__ b2,
    const float* __restrict__ W3, const float* __restrict__ b3,
    float* __restrict__ out)
{
    extern __shared__ float sm[];
    float* xs  = sm + XS_OFF;
    float* zc  = sm + ZC_OFF;
    float* w0d = sm + W0_OFF;
    float* w1d = sm + W1_OFF;
    float* w2d = sm + W2_OFF;
    float* w3d = sm + W3_OFF;
    float* bb0 = sm + B0_OFF;
    float* bb1 = sm + B1_OFF;
    float* bb2 = sm + B2_OFF;
    float* bb3 = sm + B3_OFF;

    const int c = blockIdx.x, s = blockIdx.y, tid = threadIdx.x;

    // ---- stage x (coalesced float4 reads, pad-65 shared rows) ----
    const float4* x4 = (const float4*)x;
    for (int v = tid; v < (BSZ * D) / 4; v += 128) {
        float4 val = x4[v];
        int base = v * 4;
        int b = base >> 6, i = base & 63;
        float* dst = xs + b * 65 + i;
        dst[0] = val.x; dst[1] = val.y; dst[2] = val.z; dst[3] = val.w;
    }
    // ---- stage lane-duplicated weights / biases ----
    for (int e = tid; e < 2048; e += 128) {
        float w = W0[c * 2048 + e]; w0d[2 * e] = w; w0d[2 * e + 1] = w;
    }
    for (int e = tid; e < 1024; e += 128) {
        float w = W1[c * 1024 + e]; w1d[2 * e] = w; w1d[2 * e + 1] = w;
        float v = W2[c * 1024 + e]; w2d[2 * e] = v; w2d[2 * e + 1] = v;
    }
    if (tid < 32) {
        float w = W3[c * 32 + tid]; w3d[2 * tid] = w; w3d[2 * tid + 1] = w;
        float q = b0[c * 32 + tid]; bb0[2 * tid] = q; bb0[2 * tid + 1] = q;
        q = b1[c * 32 + tid]; bb1[2 * tid] = q; bb1[2 * tid + 1] = q;
        q = b2[c * 32 + tid]; bb2[2 * tid] = q; bb2[2 * tid + 1] = q;
    }
    if (tid == 0) { float q = b3[c]; bb3[0] = q; bb3[1] = q; }
    if (tid < 64) zc[tid] = adj[s * 4096 + tid * 64 + c];
    __syncthreads();

    const u64* w0q = (const u64*)w0d;
    const u64* w1q = (const u64*)w1d;
    const u64* w2q = (const u64*)w2d;
    const u64* w3q = (const u64*)w3d;
    const u64* b0q = (const u64*)bb0;
    const u64* b1q = (const u64*)bb1;
    const u64* b2q = (const u64*)bb2;
    const u64* b3q = (const u64*)bb3;

    #pragma unroll 1
    for (int kp = 0; kp < 2; ++kp) {
        const int blo = tid + kp * 256;
        const int bhi = blo + 128;
        const float* xlo = xs + blo * 65;
        const float* xhi = xs + bhi * 65;

        // ---- layer 0: 64 -> 32, h[i] = zc[i] * x[b][i] ----
        u64 actA[32];
        #pragma unroll
        for (int o = 0; o < 32; ++o) actA[o] = b0q[o];
        #pragma unroll 4
        for (int i = 0; i < 64; ++i) {
            float zi = zc[i];
            u64 h2 = pack2(zi * xlo[i], zi * xhi[i]);
            #pragma unroll
            for (int o = 0; o < 32; ++o)
                actA[o] = fma2(w0q[o * 64 + i], h2, actA[o]);
        }
        #pragma unroll
        for (int o = 0; o < 32; ++o) actA[o] = relu2(actA[o]);

        // ---- layer 1: 32 -> 32 ----
        u64 actB[32];
        #pragma unroll
        for (int o = 0; o < 32; ++o) {
            u64 t = b1q[o];
            #pragma unroll
            for (int i = 0; i < 32; ++i)
                t = fma2(w1q[o * 32 + i], actA[i], t);
            actB[o] = relu2(t);
        }

        // ---- layer 2: 32 -> 32 ----
        #pragma unroll
        for (int o = 0; o < 32; ++o) {
            u64 t = b2q[o];
            #pragma unroll
            for (int i = 0; i < 32; ++i)
                t = fma2(w2q[o * 32 + i], actB[i], t);
            actA[o] = relu2(t);
        }

        // ---- layer 3: 32 -> 1 ----
        u64 t = b3q[0];
        #pragma unroll
        for (int i = 0; i < 32; ++i)
            t = fma2(w3q[i], actA[i], t);

        float lo, hi; unpack2(t, lo, hi);
        out[blo * (S * D) + s * D + c] = lo;
        out[bhi * (S * D) + s * D + c] = hi;
    }
}

// ---------------- launch ----------------
extern "C" void kernel_launch(void* const* d_in, const int* in_sizes, int n_in,
                              void* d_out, int out_size)
{
    const float* x  = (const float*)d_in[0];
    const float* z  = (const float*)d_in[1];
    const float* W0 = (const float*)d_in[2];
    const float* b0 = (const float*)d_in[3];
    const float* W1 = (const float*)d_in[4];
    const float* b1 = (const float*)d_in[5];
    const float* W2 = (const float*)d_in[6];
    const float* b2 = (const float*)d_in[7];
    const float* W3 = (const float*)d_in[8];
    const float* b3 = (const float*)d_in[9];

    float* out = (float*)d_out;
    float* adj = out + OUT_ELEMS;   // tuple output: (out, z_adj) concatenated

    // z_adj: 64 blocks, 48KB dynamic shared (within default limit)
    zadj_kernel<<<S, 256, 3 * 4096 * sizeof(float)>>>(z, adj);

    // fused MLP: needs >48KB dynamic shared
    cudaFuncSetAttribute(mlp_kernel, cudaFuncAttributeMaxDynamicSharedMemorySize, SMEM_BYTES);
    dim3 grid(D, S);   // (c, s)
    mlp_kernel<<<grid, 128, SMEM_BYTES>>>(x, adj,
                                          W0, b0, W1, b1, W2, b2, W3, b3,
                                          out);
}

// round 8
// speedup vs baseline: 1.6184x; 1.6184x over previous
#include <cuda_runtime.h>

// Problem constants
#define D        64
#define S        64
#define BSZ      512
#define LTW      2016          // d*(d-1)/2
#define ZROW     6112          // lt + d*d
#define OUT_ELEMS (BSZ * S * D) // 2097152, z_adj follows at this offset

typedef unsigned long long u64;
typedef ulonglong2 u64x2;

// ---------------- f32x2 packed-math helpers (sm_100+) ----------------
__device__ __forceinline__ u64 pack2(float lo, float hi) {
    u64 r; asm("mov.b64 %0, {%1,%2};" : "=l"(r) : "f"(lo), "f"(hi)); return r;
}
__device__ __forceinline__ void unpack2(u64 v, float& lo, float& hi) {
    asm("mov.b64 {%0,%1}, %2;" : "=f"(lo), "=f"(hi) : "l"(v));
}
__device__ __forceinline__ u64 fma2(u64 a, u64 b, u64 c) {
    u64 d; asm("fma.rn.f32x2 %0, %1, %2, %3;" : "=l"(d) : "l"(a), "l"(b), "l"(c)); return d;
}
__device__ __forceinline__ u64 relu2(u64 v) {
    float lo, hi; unpack2(v, lo, hi);
    lo = fmaxf(lo, 0.0f); hi = fmaxf(hi, 0.0f);
    return pack2(lo, hi);
}

// Packed-transposed x: xT2[i*256 + p] = (x[2p][i], x[2p+1][i])
__device__ u64 xT2g[64 * 256];

// ---------------- Kernel A: z_adj[s] = z_p^T @ z_lt @ z_p ----------------
__global__ void zadj_kernel(const float* __restrict__ z, float* __restrict__ adj_out) {
    extern __shared__ float sm[];
    float* lt  = sm;           // 4096
    float* p   = sm + 4096;    // 4096
    float* tmp = sm + 8192;    // 4096
    const int s   = blockIdx.x;
    const int tid = threadIdx.x;
    const float* zs = z + s * ZROW;

    for (int e = tid; e < 4096; e += 256) {
        lt[e] = 0.0f;
        p[e]  = zs[LTW + e];
    }
    __syncthreads();

    for (int k = tid; k < LTW; k += 256) {
        int i = (int)((sqrtf(8.0f * (float)k + 1.0f) + 1.0f) * 0.5f);
        while (i * (i - 1) / 2 > k)       --i;
        while ((i + 1) * i / 2 <= k)      ++i;
        int j = k - i * (i - 1) / 2;
        lt[i * 64 + j] = zs[k];
    }
    __syncthreads();

    for (int e = tid; e < 4096; e += 256) {
        int r = e >> 6, j = e & 63;
        float acc = 0.0f;
        for (int t = 0; t < r; ++t)
            acc += lt[r * 64 + t] * p[t * 64 + j];
        tmp[e] = acc;
    }
    __syncthreads();

    for (int e = tid; e < 4096; e += 256) {
        int i = e >> 6, j = e & 63;
        float acc = 0.0f;
        #pragma unroll 8
        for (int r = 0; r < 64; ++r)
            acc += p[r * 64 + i] * tmp[r * 64 + j];
        adj_out[s * 4096 + e] = acc;
    }
}

// ---------------- Kernel A2: pack/transpose x into xT2g ----------------
// coalesced reads; scattered 4B writes (128KB total, negligible)
__global__ void xpack_kernel(const float* __restrict__ x) {
    int idx = blockIdx.x * 256 + threadIdx.x;   // 0 .. 32767
    float v = x[idx];
    int b = idx >> 6, i = idx & 63;
    ((float*)xT2g)[(i * 256 + (b >> 1)) * 2 + (b & 1)] = v;
}

// ---------------- Kernel B: fused 4-layer channel MLP ----------------
// Grid: (c*2+bh, s). 128 threads; thread = one batch pair (2 batches via f32x2).
// All weights staged lane-duplicated in shared; zc folded into W0 (wz).
__global__ void __launch_bounds__(128, 3) mlp_kernel(
    const float* __restrict__ adj,
    const float* __restrict__ W0, const float* __restrict__ b0,
    const float* __restrict__ W1, const float* __restrict__ b1,
    const float* __restrict__ W2, const float* __restrict__ b2,
    const float* __restrict__ W3, const float* __restrict__ b3,
    float* __restrict__ out)
{
    __shared__ __align__(16) float wzd[4096];   // wz dup: [(i*32+o)*2]
    __shared__ __align__(16) float w1d[2048];   // [(o*32+i)*2]
    __shared__ __align__(16) float w2d[2048];
    __shared__ __align__(16) float w3d[64];
    __shared__ __align__(16) float b0d[64], b1d[64], b2d[64], b3d[2];
    __shared__ float zcs[64];
    __shared__ float wtmp[32 * 65];             // padded W0 transpose staging

    const int bx = blockIdx.x;
    const int c = bx >> 1, bh = bx & 1;
    const int s = blockIdx.y;
    const int tid = threadIdx.x;

    // ---- phase 1: zc + small weights/biases ----
    if (tid < 64) zcs[tid] = adj[s * 4096 + tid * 64 + c];
    for (int e = tid; e < 1024; e += 128) {
        float w = W1[c * 1024 + e]; w1d[2 * e] = w; w1d[2 * e + 1] = w;
        float v = W2[c * 1024 + e]; w2d[2 * e] = v; w2d[2 * e + 1] = v;
    }
    // W0 -> padded shared (coalesced LDG, conflict-free STS)
    for (int e = tid; e < 2048; e += 128) {
        int o = e >> 6, i = e & 63;
        wtmp[o * 65 + i] = W0[c * 2048 + e];
    }
    if (tid < 32) {
        float w = W3[c * 32 + tid]; w3d[2 * tid] = w; w3d[2 * tid + 1] = w;
        float q = b0[c * 32 + tid]; b0d[2 * tid] = q; b0d[2 * tid + 1] = q;
        q = b1[c * 32 + tid]; b1d[2 * tid] = q; b1d[2 * tid + 1] = q;
        q = b2[c * 32 + tid]; b2d[2 * tid] = q; b2d[2 * tid + 1] = q;
    }
    if (tid == 0) { float q = b3[c]; b3d[0] = q; b3d[1] = q; }
    __syncthreads();

    // ---- phase 2: wz[i][o] = W0[c][o][i] * zc[i], duplicated ----
    // lanes walk o (stride-65 reads conflict-free; STS.64 writes conflict-free)
    for (int e = tid; e < 2048; e += 128) {
        int o = e & 31, i = e >> 5;
        float w = wtmp[o * 65 + i] * zcs[i];
        ((u64*)wzd)[i * 32 + o] = pack2(w, w);
    }
    __syncthreads();

    const u64x2* wz2 = (const u64x2*)wzd;   // [i*16 + oq]
    const u64x2* w1q = (const u64x2*)w1d;   // [o*16 + iq]
    const u64x2* w2q = (const u64x2*)w2d;
    const u64x2* w3q = (const u64x2*)w3d;   // [iq]
    const u64* b0q = (const u64*)b0d;
    const u64* b1q = (const u64*)b1d;
    const u64* b2q = (const u64*)b2d;
    const u64* b3q = (const u64*)b3d;

    const int p = bh * 128 + tid;
    const u64* __restrict__ xp = xT2g + p;

    u64 acc[32], nxt[32];

    // ---- layer 0: 64 -> 32 (zc pre-folded into wz) ----
    #pragma unroll
    for (int o = 0; o < 32; ++o) acc[o] = b0q[o];
    #pragma unroll 8
    for (int i = 0; i < 64; ++i) {
        u64 x2 = xp[i * 256];                 // coalesced LDG.64, L2-resident
        const u64x2* wrow = wz2 + i * 16;
        #pragma unroll
        for (int oq = 0; oq < 16; ++oq) {
            u64x2 w = wrow[oq];               // LDS.128 broadcast
            acc[2 * oq]     = fma2(w.x, x2, acc[2 * oq]);
            acc[2 * oq + 1] = fma2(w.y, x2, acc[2 * oq + 1]);
        }
    }
    #pragma unroll
    for (int o = 0; o < 32; ++o) acc[o] = relu2(acc[o]);

    // ---- layer 1: 32 -> 32 ----
    #pragma unroll
    for (int o = 0; o < 32; ++o) {
        u64 t = b1q[o];
        const u64x2* wrow = w1q + o * 16;
        #pragma unroll
        for (int iq = 0; iq < 16; ++iq) {
            u64x2 w = wrow[iq];
            t = fma2(w.x, acc[2 * iq], t);
            t = fma2(w.y, acc[2 * iq + 1], t);
        }
        nxt[o] = relu2(t);
    }

    // ---- layer 2: 32 -> 32 ----
    #pragma unroll
    for (int o = 0; o < 32; ++o) {
        u64 t = b2q[o];
        const u64x2* wrow = w2q + o * 16;
        #pragma unroll
        for (int iq = 0; iq < 16; ++iq) {
            u64x2 w = wrow[iq];
            t = fma2(w.x, nxt[2 * iq], t);
            t = fma2(w.y, nxt[2 * iq + 1], t);
        }
        acc[o] = relu2(t);
    }

    // ---- layer 3: 32 -> 1 ----
    u64 t = b3q[0];
    #pragma unroll
    for (int iq = 0; iq < 16; ++iq) {
        u64x2 w = w3q[iq];
        t = fma2(w.x, acc[2 * iq], t);
        t = fma2(w.y, acc[2 * iq + 1], t);
    }

    float lo, hi; unpack2(t, lo, hi);
    const int base = s * 64 + c;
    out[(2 * p) * (S * D) + base]     = lo;
    out[(2 * p + 1) * (S * D) + base] = hi;
}

// ---------------- launch ----------------
extern "C" void kernel_launch(void* const* d_in, const int* in_sizes, int n_in,
                              void* d_out, int out_size)
{
    const float* x  = (const float*)d_in[0];
    const float* z  = (const float*)d_in[1];
    const float* W0 = (const float*)d_in[2];
    const float* b0 = (const float*)d_in[3];
    const float* W1 = (const float*)d_in[4];
    const float* b1 = (const float*)d_in[5];
    const float* W2 = (const float*)d_in[6];
    const float* b2 = (const float*)d_in[7];
    const float* W3 = (const float*)d_in[8];
    const float* b3 = (const float*)d_in[9];

    float* out = (float*)d_out;
    float* adj = out + OUT_ELEMS;   // tuple output: (out, z_adj) concatenated

    // z_adj: 64 blocks, 48KB dynamic shared
    zadj_kernel<<<S, 256, 3 * 4096 * sizeof(float)>>>(z, adj);

    // pack/transpose x (independent of zadj, same stream keeps ordering for mlp)
    xpack_kernel<<<(BSZ * D) / 256, 256>>>(x);

    // fused MLP
    dim3 grid(2 * D, S);   // (c,bh) x s
    mlp_kernel<<<grid, 128>>>(adj,
                              W0, b0, W1, b1, W2, b2, W3, b3,
                              out);
}